// round 1
// baseline (speedup 1.0000x reference)
#include <cuda_runtime.h>
#include <stdint.h>

#define NROWS 500000
#define VIN   64
#define VOUT  16
#define ROW_F (VIN * 3)    // 192 floats per input row
#define OUT_F (VOUT * 3)   // 48 floats per output row
#define WPB   8            // warps per block
#define TPB   (WPB * 32)

__global__ __launch_bounds__(TPB)
void vns_kernel(const float* __restrict__ x, float* __restrict__ out) {
    __shared__ float srow[WPB][ROW_F];
    __shared__ float sout[WPB][OUT_F];

    const int warp = threadIdx.x >> 5;
    const int lane = threadIdx.x & 31;
    const int row  = blockIdx.x * WPB + warp;
    if (row >= NROWS) return;

    // ---- coalesced load: 48 float4 per row into smem ----
    const float4* src = (const float4*)(x + (size_t)row * ROW_F);
    float4* s4 = (float4*)srow[warp];
    s4[lane] = src[lane];
    if (lane < 16) s4[32 + lane] = src[32 + lane];
    __syncwarp();

    const float* s = srow[warp];

    // ---- squared norms, bit-matching ((a*a + b*b) + c*c) ----
    unsigned long long k0, k1;
    {
        float a = s[3 * lane], b = s[3 * lane + 1], c = s[3 * lane + 2];
        float n = __fadd_rn(__fadd_rn(__fmul_rn(a, a), __fmul_rn(b, b)), __fmul_rn(c, c));
        k0 = ((unsigned long long)__float_as_uint(n) << 32) | (unsigned)(63 - lane);
        int v = lane + 32;
        a = s[3 * v]; b = s[3 * v + 1]; c = s[3 * v + 2];
        n = __fadd_rn(__fadd_rn(__fmul_rn(a, a), __fmul_rn(b, b)), __fmul_rn(c, c));
        k1 = ((unsigned long long)__float_as_uint(n) << 32) | (unsigned)(63 - v);
    }

    // ---- bitonic sort of 64 keys, descending; element i0=lane, i1=lane+32 ----
    #pragma unroll
    for (int k = 2; k <= 64; k <<= 1) {
        #pragma unroll
        for (int j = k >> 1; j > 0; j >>= 1) {
            if (j == 32) {
                // only at k==64: pair (lane, lane+32); slot0 keeps larger
                unsigned long long hi = (k0 > k1) ? k0 : k1;
                unsigned long long lo = (k0 > k1) ? k1 : k0;
                k0 = hi; k1 = lo;
            } else {
                unsigned long long p0 = __shfl_xor_sync(0xffffffffu, k0, j);
                unsigned long long p1 = __shfl_xor_sync(0xffffffffu, k1, j);
                bool low    = (lane & j) == 0;
                bool keepL0 = (((lane      ) & k) == 0) == low;
                bool keepL1 = (((lane + 32 ) & k) == 0) == low;
                k0 = keepL0 ? ((k0 > p0) ? k0 : p0) : ((k0 > p0) ? p0 : k0);
                k1 = keepL1 ? ((k1 > p1) ? k1 : p1) : ((k1 > p1) ? p1 : k1);
            }
        }
    }

    // ---- top-16 now in slot0, lanes 0..15, descending; gather into smem ----
    if (lane < 16) {
        int idx = 63 - (int)(k0 & 63ull);
        sout[warp][3 * lane + 0] = s[3 * idx + 0];
        sout[warp][3 * lane + 1] = s[3 * idx + 1];
        sout[warp][3 * lane + 2] = s[3 * idx + 2];
    }
    __syncwarp();

    // ---- coalesced store: 12 float4 per row ----
    if (lane < 12) {
        float4* d4 = (float4*)(out + (size_t)row * OUT_F);
        d4[lane] = ((const float4*)sout[warp])[lane];
    }
}

extern "C" void kernel_launch(void* const* d_in, const int* in_sizes, int n_in,
                              void* d_out, int out_size) {
    const float* x = (const float*)d_in[0];
    float* out = (float*)d_out;
    int blocks = (NROWS + WPB - 1) / WPB;
    vns_kernel<<<blocks, TPB>>>(x, out);
}

// round 2
// speedup vs baseline: 1.9915x; 1.9915x over previous
#include <cuda_runtime.h>
#include <stdint.h>

#define NROWS 500000
#define WPB   8
#define TPB   (WPB * 32)

__device__ __forceinline__ unsigned shfx(unsigned v, int j) {
    return __shfl_xor_sync(0xffffffffu, v, j);
}

__global__ __launch_bounds__(TPB)
void vns_kernel(const float* __restrict__ x, float* __restrict__ out) {
    __shared__ float srow[WPB][192];
    __shared__ float sout[WPB][48];

    const int warp = threadIdx.x >> 5;
    const int lane = threadIdx.x & 31;
    const int row  = blockIdx.x * WPB + warp;
    if (row >= NROWS) return;

    // ---- coalesced load: 48 float4 per row into smem ----
    const float4* src = (const float4*)(x + (size_t)row * 192);
    float4* s4 = (float4*)srow[warp];
    s4[lane] = src[lane];
    if (lane < 16) s4[32 + lane] = src[32 + lane];
    __syncwarp();
    const float* s = srow[warp];

    // ---- squared norms ((a*a + b*b) + c*c), as uint keys (norm >= 0) ----
    unsigned n0, n1;
    {
        float a = s[3 * lane], b = s[3 * lane + 1], c = s[3 * lane + 2];
        n0 = __float_as_uint(__fadd_rn(__fadd_rn(__fmul_rn(a, a), __fmul_rn(b, b)), __fmul_rn(c, c)));
        int e = lane + 32;
        a = s[3 * e]; b = s[3 * e + 1]; c = s[3 * e + 2];
        n1 = __float_as_uint(__fadd_rn(__fadd_rn(__fmul_rn(a, a), __fmul_rn(b, b)), __fmul_rn(c, c)));
    }

    // ---- Phase 1: value-only top-16 (cheap IMNMX compare-exchanges) ----
    // Sort k0 (elems 0..31) DESC and k1 (elems 32..63) ASC simultaneously.
    unsigned k0 = n0, k1 = n1;
    #pragma unroll
    for (int k = 2; k <= 32; k <<= 1) {
        #pragma unroll
        for (int j = k >> 1; j > 0; j >>= 1) {
            unsigned p0 = shfx(k0, j);
            unsigned p1 = shfx(k1, j);
            bool ks = ((lane & k) == 0) == ((lane & j) == 0);
            k0 = ks ? max(k0, p0) : min(k0, p0);   // -> descending
            k1 = ks ? min(k1, p1) : max(k1, p1);   // -> ascending
        }
    }
    // Bitonic split: m = elementwise max of (desc, asc) = top-32, bitonic.
    unsigned m = max(k0, k1);
    // Bitonic merge 32 -> fully sorted descending across lanes.
    #pragma unroll
    for (int j = 16; j > 0; j >>= 1) {
        unsigned p = shfx(m, j);
        bool kb = (lane & j) == 0;
        m = kb ? max(m, p) : min(m, p);
    }
    // m[lane] = (lane+1)-th largest norm. Threshold = 16th largest.
    unsigned t   = __shfl_sync(0xffffffffu, m, 15);
    unsigned nxt = __shfl_down_sync(0xffffffffu, m, 1);
    bool eq = (lane < 16) && (m == nxt);          // tie anywhere in top-17?
    bool anyTie = __ballot_sync(0xffffffffu, eq) != 0;

    if (!anyTie) {
        // ---- Phase 2 (fast path): exact, since top-17 values distinct ----
        bool sel0 = (n0 >= t);
        bool sel1 = (n1 >= t);
        // position = #{sorted values > mine} via 4-step shuffle binary search
        int c0 = 0, c1 = 0;
        #pragma unroll
        for (int sstep = 8; sstep > 0; sstep >>= 1) {
            unsigned p0 = __shfl_sync(0xffffffffu, m, c0 + sstep - 1);
            unsigned p1 = __shfl_sync(0xffffffffu, m, c1 + sstep - 1);
            if (p0 > n0) c0 += sstep;
            if (p1 > n1) c1 += sstep;
        }
        if (sel0) {
            sout[warp][3 * c0 + 0] = s[3 * lane + 0];
            sout[warp][3 * c0 + 1] = s[3 * lane + 1];
            sout[warp][3 * c0 + 2] = s[3 * lane + 2];
        }
        if (sel1) {
            int e = lane + 32;
            sout[warp][3 * c1 + 0] = s[3 * e + 0];
            sout[warp][3 * c1 + 1] = s[3 * e + 1];
            sout[warp][3 * c1 + 2] = s[3 * e + 2];
        }
    } else {
        // ---- Fallback (rare, warp-uniform): exact 64-bit keyed full sort ----
        unsigned long long K0 = ((unsigned long long)n0 << 32) | (unsigned)(63 - lane);
        unsigned long long K1 = ((unsigned long long)n1 << 32) | (unsigned)(31 - lane); // 63-(lane+32)
        #pragma unroll
        for (int k = 2; k <= 64; k <<= 1) {
            #pragma unroll
            for (int j = k >> 1; j > 0; j >>= 1) {
                if (j == 32) {
                    unsigned long long hi = (K0 > K1) ? K0 : K1;
                    unsigned long long lo = (K0 > K1) ? K1 : K0;
                    K0 = hi; K1 = lo;
                } else {
                    unsigned long long p0 = __shfl_xor_sync(0xffffffffu, K0, j);
                    unsigned long long p1 = __shfl_xor_sync(0xffffffffu, K1, j);
                    bool low = (lane & j) == 0;
                    bool L0 = (((lane     ) & k) == 0) == low;
                    bool L1 = (((lane + 32) & k) == 0) == low;
                    K0 = L0 ? ((K0 > p0) ? K0 : p0) : ((K0 > p0) ? p0 : K0);
                    K1 = L1 ? ((K1 > p1) ? K1 : p1) : ((K1 > p1) ? p1 : K1);
                }
            }
        }
        if (lane < 16) {
            int idx = 63 - (int)(K0 & 63ull);
            sout[warp][3 * lane + 0] = s[3 * idx + 0];
            sout[warp][3 * lane + 1] = s[3 * idx + 1];
            sout[warp][3 * lane + 2] = s[3 * idx + 2];
        }
    }
    __syncwarp();

    // ---- coalesced store: 12 float4 per row ----
    if (lane < 12) {
        float4* d4 = (float4*)(out + (size_t)row * 48);
        d4[lane] = ((const float4*)sout[warp])[lane];
    }
}

extern "C" void kernel_launch(void* const* d_in, const int* in_sizes, int n_in,
                              void* d_out, int out_size) {
    const float* x = (const float*)d_in[0];
    float* out = (float*)d_out;
    int blocks = (NROWS + WPB - 1) / WPB;
    vns_kernel<<<blocks, TPB>>>(x, out);
}

// round 3
// speedup vs baseline: 2.2310x; 1.1203x over previous
#include <cuda_runtime.h>
#include <stdint.h>

#define NROWS 500000
#define WPB   8
#define TPB   (WPB * 32)

__device__ __forceinline__ float shfx_f(float v, int j) {
    return __shfl_xor_sync(0xffffffffu, v, j);
}

__global__ __launch_bounds__(TPB)
void vns_kernel(const float* __restrict__ x, float* __restrict__ out) {
    const int lane = threadIdx.x & 31;
    const int row  = blockIdx.x * WPB + (threadIdx.x >> 5);
    if (row >= NROWS) return;

    // ---- lane holds vectors 2*lane and 2*lane+1: floats [6*lane, 6*lane+6) ----
    const float2* src = (const float2*)(x + (size_t)row * 192) + 3 * lane;
    float2 p0 = src[0];
    float2 p1 = src[1];
    float2 p2 = src[2];
    float v0 = p0.x, v1 = p0.y, v2 = p1.x;   // vector 2*lane
    float v3 = p1.y, v4 = p2.x, v5 = p2.y;   // vector 2*lane+1

    // ---- squared norms, bit-matching ((a*a + b*b) + c*c) ----
    float n0 = __fadd_rn(__fadd_rn(__fmul_rn(v0, v0), __fmul_rn(v1, v1)), __fmul_rn(v2, v2));
    float n1 = __fadd_rn(__fadd_rn(__fmul_rn(v3, v3), __fmul_rn(v4, v4)), __fmul_rn(v5, v5));

    // ---- Phase 1: value-only sort (FMNMX on FMA pipe). Slot0 DESC, slot1 ASC. ----
    float k0 = n0, k1 = n1;
    #pragma unroll
    for (int k = 2; k <= 32; k <<= 1) {
        #pragma unroll
        for (int j = k >> 1; j > 0; j >>= 1) {
            float q0 = shfx_f(k0, j);
            float q1 = shfx_f(k1, j);
            bool ks = ((lane & k) == 0) == ((lane & j) == 0);
            k0 = ks ? fmaxf(k0, q0) : fminf(k0, q0);
            k1 = ks ? fminf(k1, q1) : fmaxf(k1, q1);
        }
    }
    // Elementwise max of (desc, asc) = top-32 multiset, bitonic. Merge desc.
    float m = fmaxf(k0, k1);
    #pragma unroll
    for (int j = 16; j > 0; j >>= 1) {
        float q = shfx_f(m, j);
        m = ((lane & j) == 0) ? fmaxf(m, q) : fminf(m, q);
    }
    // m[lane] = (lane+1)-th largest. Threshold = 16th; detect ties in top-17.
    float t   = __shfl_sync(0xffffffffu, m, 15);
    float nxt = __shfl_down_sync(0xffffffffu, m, 1);
    bool eq = (lane < 16) && (m == nxt);
    bool anyTie = __ballot_sync(0xffffffffu, eq) != 0;

    float* dst = out + (size_t)row * 48;

    if (!anyTie) {
        // ---- fast path: top-17 distinct -> positions via shuffle binary search ----
        int c0 = 0, c1 = 0;
        #pragma unroll
        for (int sstep = 8; sstep > 0; sstep >>= 1) {
            float q0 = __shfl_sync(0xffffffffu, m, c0 + sstep - 1);
            float q1 = __shfl_sync(0xffffffffu, m, c1 + sstep - 1);
            if (q0 > n0) c0 += sstep;
            if (q1 > n1) c1 += sstep;
        }
        if (n0 >= t) {
            dst[3 * c0 + 0] = v0;
            dst[3 * c0 + 1] = v1;
            dst[3 * c0 + 2] = v2;
        }
        if (n1 >= t) {
            dst[3 * c1 + 0] = v3;
            dst[3 * c1 + 1] = v4;
            dst[3 * c1 + 2] = v5;
        }
    } else {
        // ---- exact fallback (rare, warp-uniform): 64-bit keyed full sort ----
        // elements: A = 2*lane (K0), B = 2*lane+1 (K1); low bits = 63 - idx
        unsigned long long K0 = ((unsigned long long)__float_as_uint(n0) << 32) | (unsigned)(63 - 2 * lane);
        unsigned long long K1 = ((unsigned long long)__float_as_uint(n1) << 32) | (unsigned)(62 - 2 * lane);
        #pragma unroll
        for (int k = 2; k <= 64; k <<= 1) {
            #pragma unroll
            for (int j = k >> 1; j > 0; j >>= 1) {
                bool dirTop = ((lane & (k >> 1)) == 0);   // (e & k)==0 for both elems (k>=2)
                if (j == 1) {
                    // in-lane CE between A (even pos, low=true) and B (odd pos)
                    unsigned long long hi = (K0 > K1) ? K0 : K1;
                    unsigned long long lo = (K0 > K1) ? K1 : K0;
                    K0 = dirTop ? hi : lo;
                    K1 = dirTop ? lo : hi;
                } else {
                    int lj = j >> 1;
                    unsigned long long q0 = __shfl_xor_sync(0xffffffffu, K0, lj);
                    unsigned long long q1 = __shfl_xor_sync(0xffffffffu, K1, lj);
                    bool low  = ((lane & lj) == 0);       // (e & j)==0 for both elems
                    bool keep = (dirTop == low);
                    K0 = keep ? ((K0 > q0) ? K0 : q0) : ((K0 > q0) ? q0 : K0);
                    K1 = keep ? ((K1 > q1) ? K1 : q1) : ((K1 > q1) ? q1 : K1);
                }
            }
        }
        // Sorted desc: position 2*lane -> K0, 2*lane+1 -> K1. Lane p<16 takes pos p.
        unsigned long long Ka = __shfl_sync(0xffffffffu, K0, lane >> 1);
        unsigned long long Kb = __shfl_sync(0xffffffffu, K1, lane >> 1);
        unsigned long long Kp = (lane & 1) ? Kb : Ka;
        int idx = 63 - (int)(Kp & 63ull);                 // source element for my position
        int srcl = idx >> 1;
        // fetch source vector's registers via shuffles (all lanes participate)
        float a0 = __shfl_sync(0xffffffffu, v0, srcl);
        float a1 = __shfl_sync(0xffffffffu, v1, srcl);
        float a2 = __shfl_sync(0xffffffffu, v2, srcl);
        float b0 = __shfl_sync(0xffffffffu, v3, srcl);
        float b1 = __shfl_sync(0xffffffffu, v4, srcl);
        float b2 = __shfl_sync(0xffffffffu, v5, srcl);
        if (lane < 16) {
            bool oddv = (idx & 1);
            dst[3 * lane + 0] = oddv ? b0 : a0;
            dst[3 * lane + 1] = oddv ? b1 : a1;
            dst[3 * lane + 2] = oddv ? b2 : a2;
        }
    }
}

extern "C" void kernel_launch(void* const* d_in, const int* in_sizes, int n_in,
                              void* d_out, int out_size) {
    const float* x = (const float*)d_in[0];
    float* out = (float*)d_out;
    int blocks = (NROWS + WPB - 1) / WPB;
    vns_kernel<<<blocks, TPB>>>(x, out);
}